// round 1
// baseline (speedup 1.0000x reference)
#include <cuda_runtime.h>
#include <math.h>

#define T_LEN 1024
#define BATCH 16
#define DIM   1024
#define NBLK  128
#define EPSF  1e-8f
#define MAXRAD 0.999f
#define SLAB  (BATCH * DIM)              // 16384
#define OFF_H ((size_t)T_LEN * SLAB)     // outs first, then h_all

// ---------------- device scratch (no allocs allowed) ----------------
__device__ float    g_Xp[(size_t)T_LEN * SLAB];  // 64 MB: x @ Wx^T + b
__device__ float    g_h[2][SLAB];                // double-buffered hidden state
__device__ float    g_u[DIM];
__device__ float    g_v[DIM];
__device__ float    g_part[NBLK];
__device__ unsigned g_bar;

// ---------------- init: reset barrier, seed u0 ----------------
__global__ void init_kernel(const float* __restrict__ u0) {
    if (threadIdx.x == 0) g_bar = 0u;
    for (int i = threadIdx.x; i < DIM; i += blockDim.x) g_u[i] = u0[i];
}

// ---------------- Xp = x @ Wx^T + b  (fp32 SGEMM, NT) ----------------
// A [16384,1024] row-major, Wn [1024,1024] row-major; C[m][n] = sum_k A[m][k]*Wn[n][k] + b[n]
__global__ __launch_bounds__(256) void xp_gemm(const float* __restrict__ A,
                                               const float* __restrict__ Wn,
                                               const float* __restrict__ bias) {
    __shared__ float As[8][132];
    __shared__ float Bs[8][132];
    const int bn = blockIdx.x;   // 0..7
    const int bm = blockIdx.y;   // 0..127
    const int tid = threadIdx.x;
    const int tx = tid & 15, ty = tid >> 4;
    const int m0 = bm * 128, n0 = bn * 128;

    float acc[8][8];
#pragma unroll
    for (int i = 0; i < 8; i++)
#pragma unroll
        for (int j = 0; j < 8; j++) acc[i][j] = 0.f;

    const int lm = tid >> 1;
    const int lk = (tid & 1) * 4;
    const float* ap = A  + (size_t)(m0 + lm) * DIM + lk;
    const float* bp = Wn + (size_t)(n0 + lm) * DIM + lk;

    for (int k0 = 0; k0 < DIM; k0 += 8) {
        float4 av = *(const float4*)(ap + k0);
        float4 bv = *(const float4*)(bp + k0);
        As[lk + 0][lm] = av.x; As[lk + 1][lm] = av.y; As[lk + 2][lm] = av.z; As[lk + 3][lm] = av.w;
        Bs[lk + 0][lm] = bv.x; Bs[lk + 1][lm] = bv.y; Bs[lk + 2][lm] = bv.z; Bs[lk + 3][lm] = bv.w;
        __syncthreads();
#pragma unroll
        for (int k = 0; k < 8; k++) {
            float a[8], b2[8];
            *(float4*)&a[0]  = *(const float4*)&As[k][ty * 8];
            *(float4*)&a[4]  = *(const float4*)&As[k][ty * 8 + 4];
            *(float4*)&b2[0] = *(const float4*)&Bs[k][tx * 8];
            *(float4*)&b2[4] = *(const float4*)&Bs[k][tx * 8 + 4];
#pragma unroll
            for (int i = 0; i < 8; i++)
#pragma unroll
                for (int j = 0; j < 8; j++) acc[i][j] = fmaf(a[i], b2[j], acc[i][j]);
        }
        __syncthreads();
    }
#pragma unroll
    for (int i = 0; i < 8; i++) {
        const int m = m0 + ty * 8 + i;
        float* cr = g_Xp + (size_t)m * DIM + n0 + tx * 8;
#pragma unroll
        for (int j = 0; j < 8; j++) cr[j] = acc[i][j] + bias[n0 + tx * 8 + j];
    }
}

// ---------------- grid barrier (persistent kernel) ----------------
__device__ __forceinline__ void gridbar(int& seq) {
    seq++;
    __syncthreads();
    if (threadIdx.x == 0) {
        __threadfence();
        atomicAdd(&g_bar, 1u);
        const unsigned tgt = (unsigned)seq * NBLK;
        while (*((volatile unsigned*)&g_bar) < tgt) { }
        __threadfence();
    }
    __syncthreads();
}

// ---------------- persistent scan kernel ----------------
__global__ __launch_bounds__(256) void scan_kernel(const float* __restrict__ z,
                                                   const float* __restrict__ h0,
                                                   const float* __restrict__ W_h,
                                                   const float* __restrict__ log_radii,
                                                   float* __restrict__ out) {
    __shared__ float scratch[256 * 17];  // K-split reduction, pitch 17 vs bank conflicts
    __shared__ float sred[64];

    const int tid  = threadIdx.x;
    const int bid  = blockIdx.x;
    const int lane = tid & 31;
    const int warp = tid >> 5;
    int seq = 0;

    // ======== phase 0: power iteration (3 iters) ========
    float sigma = 0.f;
    for (int it = 0; it < 3; it++) {
        // v_raw = W^T u ; block owns columns [bid*8, bid*8+8)
        {
            const int j0 = bid * 8;
            float sj[8];
#pragma unroll
            for (int q = 0; q < 8; q++) sj[q] = 0.f;
            for (int i = warp * 32 + lane; i < DIM; i += 256) {
                const float ui = __ldcg(&g_u[i]);
                const float* wr = W_h + (size_t)i * DIM + j0;
                float4 w0 = *(const float4*)wr;
                float4 w1 = *(const float4*)(wr + 4);
                sj[0] = fmaf(w0.x, ui, sj[0]); sj[1] = fmaf(w0.y, ui, sj[1]);
                sj[2] = fmaf(w0.z, ui, sj[2]); sj[3] = fmaf(w0.w, ui, sj[3]);
                sj[4] = fmaf(w1.x, ui, sj[4]); sj[5] = fmaf(w1.y, ui, sj[5]);
                sj[6] = fmaf(w1.z, ui, sj[6]); sj[7] = fmaf(w1.w, ui, sj[7]);
            }
#pragma unroll
            for (int q = 0; q < 8; q++)
#pragma unroll
                for (int o = 16; o > 0; o >>= 1) sj[q] += __shfl_xor_sync(0xffffffffu, sj[q], o);
            if (lane == 0) {
#pragma unroll
                for (int q = 0; q < 8; q++) sred[warp * 8 + q] = sj[q];
            }
            __syncthreads();
            if (tid < 8) {
                float s = 0.f;
#pragma unroll
                for (int w = 0; w < 8; w++) s += sred[w * 8 + tid];
                g_v[j0 + tid] = s;
                scratch[tid] = s * s;
            }
            __syncthreads();
            if (tid == 0) {
                float s = 0.f;
#pragma unroll
                for (int q = 0; q < 8; q++) s += scratch[q];
                g_part[bid] = s;
            }
        }
        gridbar(seq);
        {   // norm(v) deterministically, normalize own segment
            if (tid == 0) {
                float s = 0.f;
                for (int q = 0; q < NBLK; q++) s += __ldcg(&g_part[q]);
                sred[0] = sqrtf(s);
            }
            __syncthreads();
            const float nrm = sred[0];
            if (tid < 8) g_v[bid * 8 + tid] = __ldcg(&g_v[bid * 8 + tid]) / (nrm + EPSF);
        }
        gridbar(seq);
        // u_raw = W v ; block owns rows [bid*8, bid*8+8), one warp per row
        {
            const int i = bid * 8 + warp;
            float s = 0.f;
            const float* wr = W_h + (size_t)i * DIM;
            for (int j = lane * 4; j < DIM; j += 128) {
                float4 wv = *(const float4*)(wr + j);
                float4 vv = __ldcg((const float4*)(g_v + j));
                s = fmaf(wv.x, vv.x, s); s = fmaf(wv.y, vv.y, s);
                s = fmaf(wv.z, vv.z, s); s = fmaf(wv.w, vv.w, s);
            }
#pragma unroll
            for (int o = 16; o > 0; o >>= 1) s += __shfl_xor_sync(0xffffffffu, s, o);
            if (lane == 0) { g_u[i] = s; sred[warp] = s * s; }
            __syncthreads();
            if (tid == 0) {
                float ss = 0.f;
#pragma unroll
                for (int w = 0; w < 8; w++) ss += sred[w];
                g_part[bid] = ss;
            }
        }
        gridbar(seq);
        {   // norm(u); normalize; on last iter sigma = ||Wv||^2/(||Wv||+eps) == |u·W·v|
            if (tid == 0) {
                float s = 0.f;
                for (int q = 0; q < NBLK; q++) s += __ldcg(&g_part[q]);
                sred[0] = s;
            }
            __syncthreads();
            const float sumsq = sred[0];
            const float nrm = sqrtf(sumsq);
            if (tid < 8) g_u[bid * 8 + tid] = __ldcg(&g_u[bid * 8 + tid]) / (nrm + EPSF);
            if (it == 2) sigma = sumsq / (nrm + EPSF);
        }
        gridbar(seq);
    }

    // ======== phase 1: W_h_eff rows into registers ========
    // block = (batch group bg of 8, dim group dg of 16); thread = (dp: 2 dims, ks: K-slice)
    const int bg = bid & 1;
    const int dg = bid >> 1;
    const int dgbase = dg * 16;
    const int bgbase = bg * 8;
    const int dp = tid & 7;
    const int ks = tid >> 3;   // 0..31, owns k = j*128 + ks*4 + {0..3}
    const int d0 = dgbase + 2 * dp;
    const int d1 = d0 + 1;

    float sc0, sc1;
    {
        const float r0 = MAXRAD / (1.f + expf(-log_radii[d0]));
        const float r1 = MAXRAD / (1.f + expf(-log_radii[d1]));
        sc0 = r0 / (sigma + EPSF);
        sc1 = r1 / (sigma + EPSF);
    }
    float w0[32], w1[32];
#pragma unroll
    for (int j = 0; j < 8; j++) {
        const int k = j * 128 + ks * 4;
        float4 a = *(const float4*)(W_h + (size_t)d0 * DIM + k);
        float4 c = *(const float4*)(W_h + (size_t)d1 * DIM + k);
        w0[j * 4 + 0] = a.x * sc0; w0[j * 4 + 1] = a.y * sc0;
        w0[j * 4 + 2] = a.z * sc0; w0[j * 4 + 3] = a.w * sc0;
        w1[j * 4 + 0] = c.x * sc1; w1[j * 4 + 1] = c.y * sc1;
        w1[j * 4 + 2] = c.z * sc1; w1[j * 4 + 3] = c.w * sc1;
    }

    // h0 -> g_h[0] and h_all[0]
    if (tid < 128) {
        const int idx = bid * 128 + tid;
        const float hv = h0[idx];
        g_h[0][idx] = hv;
        out[OFF_H + idx] = hv;
    }
    gridbar(seq);

    // collector thread mapping (tid < 128): coalesced over d
    const bool is_col = tid < 128;
    const int col_b  = bgbase + (tid >> 4);
    const int col_d  = dgbase + (tid & 15);
    const int col_off = col_b * DIM + col_d;
    const int col_dp = (tid & 15) >> 1;
    const int col_r  = ((tid & 1) << 3) + (tid >> 4);  // di*8 + b

    // ======== phase 2: the scan ========
    for (int t = 0; t < T_LEN; t++) {
        float xp = 0.f, zv = 0.f;
        if (is_col) {
            const size_t gi = (size_t)t * SLAB + col_off;
            xp = g_Xp[gi];
            zv = z[gi];
        }
        const float4* hp = (const float4*)(g_h[t & 1]) + (size_t)bgbase * (DIM / 4);
        float acc0[8], acc1[8];
#pragma unroll
        for (int b = 0; b < 8; b++) { acc0[b] = 0.f; acc1[b] = 0.f; }
#pragma unroll
        for (int j = 0; j < 8; j++) {
            const int ko = j * 32 + ks;
#pragma unroll
            for (int b = 0; b < 8; b++) {
                float4 hv = __ldcg(hp + b * (DIM / 4) + ko);
                acc0[b] = fmaf(w0[4 * j + 0], hv.x, acc0[b]);
                acc0[b] = fmaf(w0[4 * j + 1], hv.y, acc0[b]);
                acc0[b] = fmaf(w0[4 * j + 2], hv.z, acc0[b]);
                acc0[b] = fmaf(w0[4 * j + 3], hv.w, acc0[b]);
                acc1[b] = fmaf(w1[4 * j + 0], hv.x, acc1[b]);
                acc1[b] = fmaf(w1[4 * j + 1], hv.y, acc1[b]);
                acc1[b] = fmaf(w1[4 * j + 2], hv.z, acc1[b]);
                acc1[b] = fmaf(w1[4 * j + 3], hv.w, acc1[b]);
            }
        }
#pragma unroll
        for (int q = 0; q < 8; q++) {
            scratch[tid * 17 + q]     = acc0[q];
            scratch[tid * 17 + 8 + q] = acc1[q];
        }
        __syncthreads();
        if (is_col) {
            float s = 0.f;
#pragma unroll
            for (int q = 0; q < 32; q++) s += scratch[(q * 8 + col_dp) * 17 + col_r];
            const float pre  = s + xp;
            const float hnew = tanhf(pre);
            g_h[(t + 1) & 1][col_off] = hnew;
            out[OFF_H + (size_t)(t + 1) * SLAB + col_off] = hnew;
            const float sg = 1.f / (1.f + expf(-zv));
            out[(size_t)t * SLAB + col_off] = hnew * zv * sg;
        }
        gridbar(seq);
    }
}

// ---------------- launcher ----------------
extern "C" void kernel_launch(void* const* d_in, const int* in_sizes, int n_in,
                              void* d_out, int out_size) {
    const float* x  = (const float*)d_in[0];
    const float* z  = (const float*)d_in[1];
    const float* h0 = (const float*)d_in[2];
    const float* Wx = (const float*)d_in[3];
    const float* Wh = (const float*)d_in[4];
    const float* lr = (const float*)d_in[5];
    const float* bb = (const float*)d_in[6];
    const float* u0 = (const float*)d_in[7];
    float* out = (float*)d_out;
    (void)x; (void)in_sizes; (void)n_in; (void)out_size;

    init_kernel<<<1, 256>>>(u0);
    xp_gemm<<<dim3(8, 128), 256>>>(x, Wx, bb);
    scan_kernel<<<NBLK, 256>>>(z, h0, Wh, lr, out);
}

// round 4
// speedup vs baseline: 1.8259x; 1.8259x over previous
#include <cuda_runtime.h>
#include <math.h>

#define T_LEN 1024
#define BATCH 16
#define DIM   1024
#define NBLK  128
#define GRPB  64
#define EPSF  1e-8f
#define MAXRAD 0.999f
#define SLAB  (BATCH * DIM)              // 16384
#define OFF_H ((size_t)T_LEN * SLAB)     // outs first, then h_all

// ---------------- device scratch (no allocs allowed) ----------------
__device__ float    g_Xp[(size_t)T_LEN * SLAB];  // 64 MB: x @ Wx^T + b
__device__ float    g_h[2][SLAB];                // double-buffered hidden state
__device__ float    g_u[DIM];
__device__ float    g_v[DIM];
__device__ float    g_part[NBLK];
__device__ unsigned g_bar;
__device__ unsigned g_barg[2];

// ---------------- f32x2 helpers (sm_103a packed FFMA2) ----------------
#define FMA2(d, a, b) asm("fma.rn.f32x2 %0, %1, %2, %0;" : "+l"(d) : "l"(a), "l"(b))

__device__ __forceinline__ unsigned long long pk2(float lo, float hi) {
    unsigned long long r;
    asm("mov.b64 %0, {%1, %2};" : "=l"(r) : "f"(lo), "f"(hi));
    return r;
}
__device__ __forceinline__ float2 upk2(unsigned long long v) {
    float lo, hi;
    asm("mov.b64 {%0, %1}, %2;" : "=f"(lo), "=f"(hi) : "l"(v));
    return make_float2(lo, hi);
}

// ---------------- init: reset barriers, seed u0 ----------------
__global__ void init_kernel(const float* __restrict__ u0) {
    if (threadIdx.x == 0) { g_bar = 0u; g_barg[0] = 0u; g_barg[1] = 0u; }
    for (int i = threadIdx.x; i < DIM; i += blockDim.x) g_u[i] = u0[i];
}

// ---------------- Xp = x @ Wx^T + b  (fp32 SGEMM w/ FFMA2, NT) ----------------
__global__ __launch_bounds__(256) void xp_gemm(const float* __restrict__ A,
                                               const float* __restrict__ Wn,
                                               const float* __restrict__ bias) {
    __shared__ float As[8][132];
    __shared__ float Bs[8][132];
    const int bn = blockIdx.x;   // 0..7
    const int bm = blockIdx.y;   // 0..127
    const int tid = threadIdx.x;
    const int tx = tid & 15, ty = tid >> 4;
    const int m0 = bm * 128, n0 = bn * 128;

    unsigned long long acc2[8][4];
#pragma unroll
    for (int i = 0; i < 8; i++)
#pragma unroll
        for (int j = 0; j < 4; j++) acc2[i][j] = 0ull;

    const int lm = tid >> 1;
    const int lk = (tid & 1) * 4;
    const float* ap = A  + (size_t)(m0 + lm) * DIM + lk;
    const float* bp = Wn + (size_t)(n0 + lm) * DIM + lk;

    for (int k0 = 0; k0 < DIM; k0 += 8) {
        float4 av = *(const float4*)(ap + k0);
        float4 bv = *(const float4*)(bp + k0);
        As[lk + 0][lm] = av.x; As[lk + 1][lm] = av.y; As[lk + 2][lm] = av.z; As[lk + 3][lm] = av.w;
        Bs[lk + 0][lm] = bv.x; Bs[lk + 1][lm] = bv.y; Bs[lk + 2][lm] = bv.z; Bs[lk + 3][lm] = bv.w;
        __syncthreads();
#pragma unroll
        for (int k = 0; k < 8; k++) {
            float a[8];
            *(float4*)&a[0] = *(const float4*)&As[k][ty * 8];
            *(float4*)&a[4] = *(const float4*)&As[k][ty * 8 + 4];
            ulonglong2 t0 = *(const ulonglong2*)&Bs[k][tx * 8];
            ulonglong2 t1 = *(const ulonglong2*)&Bs[k][tx * 8 + 4];
#pragma unroll
            for (int i = 0; i < 8; i++) {
                unsigned long long ai = pk2(a[i], a[i]);
                FMA2(acc2[i][0], ai, t0.x);
                FMA2(acc2[i][1], ai, t0.y);
                FMA2(acc2[i][2], ai, t1.x);
                FMA2(acc2[i][3], ai, t1.y);
            }
        }
        __syncthreads();
    }
#pragma unroll
    for (int i = 0; i < 8; i++) {
        const int m = m0 + ty * 8 + i;
        float* cr = g_Xp + (size_t)m * DIM + n0 + tx * 8;
        const float* bs = bias + n0 + tx * 8;
#pragma unroll
        for (int j = 0; j < 4; j++) {
            float2 p = upk2(acc2[i][j]);
            cr[2 * j + 0] = p.x + bs[2 * j + 0];
            cr[2 * j + 1] = p.y + bs[2 * j + 1];
        }
    }
}

// ---------------- grid barriers ----------------
__device__ __forceinline__ void gridbar(int& seq) {
    seq++;
    __syncthreads();
    if (threadIdx.x == 0) {
        __threadfence();
        atomicAdd(&g_bar, 1u);
        const unsigned tgt = (unsigned)seq * NBLK;
        while (*((volatile unsigned*)&g_bar) < tgt) { }
        __threadfence();
    }
    __syncthreads();
}
__device__ __forceinline__ void groupbar(int& gseq, int grp) {
    gseq++;
    __syncthreads();
    if (threadIdx.x == 0) {
        __threadfence();
        atomicAdd(&g_barg[grp], 1u);
        const unsigned tgt = (unsigned)gseq * GRPB;
        while (*((volatile unsigned*)&g_barg[grp]) < tgt) { }
        __threadfence();
    }
    __syncthreads();
}

// ---------------- persistent scan kernel ----------------
__global__ __launch_bounds__(256) void scan_kernel(const float* __restrict__ z,
                                                   const float* __restrict__ h0,
                                                   const float* __restrict__ W_h,
                                                   const float* __restrict__ log_radii,
                                                   float* __restrict__ out) {
    __shared__ float smem_buf[8192];   // 32KB: h stage, then reduction scratch (aliased)
    __shared__ float sred[64];
    float* scratch = smem_buf;

    const int tid  = threadIdx.x;
    const int bid  = blockIdx.x;
    const int lane = tid & 31;
    const int warp = tid >> 5;
    int seq = 0;

    // ======== phase 0: power iteration (3 iters) ========
    float sigma = 0.f;
    for (int it = 0; it < 3; it++) {
        {   // v_raw = W^T u ; block owns columns [bid*8, bid*8+8)
            const int j0 = bid * 8;
            float sj[8];
#pragma unroll
            for (int q = 0; q < 8; q++) sj[q] = 0.f;
            for (int i = warp * 32 + lane; i < DIM; i += 256) {
                const float ui = __ldcg(&g_u[i]);
                const float* wr = W_h + (size_t)i * DIM + j0;
                float4 w0 = *(const float4*)wr;
                float4 w1 = *(const float4*)(wr + 4);
                sj[0] = fmaf(w0.x, ui, sj[0]); sj[1] = fmaf(w0.y, ui, sj[1]);
                sj[2] = fmaf(w0.z, ui, sj[2]); sj[3] = fmaf(w0.w, ui, sj[3]);
                sj[4] = fmaf(w1.x, ui, sj[4]); sj[5] = fmaf(w1.y, ui, sj[5]);
                sj[6] = fmaf(w1.z, ui, sj[6]); sj[7] = fmaf(w1.w, ui, sj[7]);
            }
#pragma unroll
            for (int q = 0; q < 8; q++)
#pragma unroll
                for (int o = 16; o > 0; o >>= 1) sj[q] += __shfl_xor_sync(0xffffffffu, sj[q], o);
            if (lane == 0) {
#pragma unroll
                for (int q = 0; q < 8; q++) sred[warp * 8 + q] = sj[q];
            }
            __syncthreads();
            if (tid < 8) {
                float s = 0.f;
#pragma unroll
                for (int w = 0; w < 8; w++) s += sred[w * 8 + tid];
                g_v[j0 + tid] = s;
                scratch[tid] = s * s;
            }
            __syncthreads();
            if (tid == 0) {
                float s = 0.f;
#pragma unroll
                for (int q = 0; q < 8; q++) s += scratch[q];
                g_part[bid] = s;
            }
        }
        gridbar(seq);
        {   // norm(v), normalize own segment
            if (tid == 0) {
                float s = 0.f;
                for (int q = 0; q < NBLK; q++) s += __ldcg(&g_part[q]);
                sred[0] = sqrtf(s);
            }
            __syncthreads();
            const float nrm = sred[0];
            if (tid < 8) g_v[bid * 8 + tid] = __ldcg(&g_v[bid * 8 + tid]) / (nrm + EPSF);
        }
        gridbar(seq);
        {   // u_raw = W v ; one warp per row
            const int i = bid * 8 + warp;
            float s = 0.f;
            const float* wr = W_h + (size_t)i * DIM;
            for (int j = lane * 4; j < DIM; j += 128) {
                float4 wv = *(const float4*)(wr + j);
                float4 vv = __ldcg((const float4*)(g_v + j));
                s = fmaf(wv.x, vv.x, s); s = fmaf(wv.y, vv.y, s);
                s = fmaf(wv.z, vv.z, s); s = fmaf(wv.w, vv.w, s);
            }
#pragma unroll
            for (int o = 16; o > 0; o >>= 1) s += __shfl_xor_sync(0xffffffffu, s, o);
            if (lane == 0) { g_u[i] = s; sred[warp] = s * s; }
            __syncthreads();
            if (tid == 0) {
                float ss = 0.f;
#pragma unroll
                for (int w = 0; w < 8; w++) ss += sred[w];
                g_part[bid] = ss;
            }
        }
        gridbar(seq);
        {   // norm(u); sigma = ||Wv||^2/(||Wv||+eps) == |u·W·v| on last iter
            if (tid == 0) {
                float s = 0.f;
                for (int q = 0; q < NBLK; q++) s += __ldcg(&g_part[q]);
                sred[0] = s;
            }
            __syncthreads();
            const float sumsq = sred[0];
            const float nrm = sqrtf(sumsq);
            if (tid < 8) g_u[bid * 8 + tid] = __ldcg(&g_u[bid * 8 + tid]) / (nrm + EPSF);
            if (it == 2) sigma = sumsq / (nrm + EPSF);
        }
        gridbar(seq);
    }

    // ======== phase 1: W_h_eff rows into registers (packed over k) ========
    const int bg = bid & 1;
    const int dg = bid >> 1;
    const int dgbase = dg * 16;
    const int bgbase = bg * 8;
    const int dp = tid & 7;
    const int ks = tid >> 3;   // 0..31, owns k = j*128 + ks*4 + {0..3}
    const int d0 = dgbase + 2 * dp;
    const int d1 = d0 + 1;

    float sc0, sc1;
    {
        const float r0 = MAXRAD / (1.f + expf(-log_radii[d0]));
        const float r1 = MAXRAD / (1.f + expf(-log_radii[d1]));
        sc0 = r0 / (sigma + EPSF);
        sc1 = r1 / (sigma + EPSF);
    }
    unsigned long long w0p[16], w1p[16];
#pragma unroll
    for (int j = 0; j < 8; j++) {
        const int k = j * 128 + ks * 4;
        float4 a = *(const float4*)(W_h + (size_t)d0 * DIM + k);
        float4 c = *(const float4*)(W_h + (size_t)d1 * DIM + k);
        w0p[2 * j + 0] = pk2(a.x * sc0, a.y * sc0);
        w0p[2 * j + 1] = pk2(a.z * sc0, a.w * sc0);
        w1p[2 * j + 0] = pk2(c.x * sc1, c.y * sc1);
        w1p[2 * j + 1] = pk2(c.z * sc1, c.w * sc1);
    }

    // h0 -> g_h[0] and h_all[0]
    if (tid < 128) {
        const int idx = bid * 128 + tid;
        const float hv = h0[idx];
        g_h[0][idx] = hv;
        out[OFF_H + idx] = hv;
    }
    gridbar(seq);   // full barrier: h0 writes cross batch groups

    // collector mapping (tid < 128): coalesced over d
    const bool is_col = tid < 128;
    const int col_off = (bgbase + (tid >> 4)) * DIM + dgbase + (tid & 15);
    const int col_dp  = (tid & 15) >> 1;
    const int col_r   = ((tid & 1) << 3) + (tid >> 4);  // di*8 + b

    int gseq = 0;
    // ======== phase 2: the scan ========
    for (int t = 0; t < T_LEN; t++) {
        float xp = 0.f, zv = 0.f;
        if (is_col) {
            const size_t gi = (size_t)t * SLAB + col_off;
            xp = g_Xp[gi];
            zv = z[gi];
        }
        // stage h[t] for this batch group into smem (32KB, coalesced)
        {
            const float4* src = (const float4*)(g_h[t & 1] + bgbase * DIM);
            float4* dst = (float4*)smem_buf;
#pragma unroll
            for (int q = 0; q < 8; q++) dst[tid + q * 256] = __ldcg(src + tid + q * 256);
        }
        __syncthreads();

        const ulonglong2* hp2 = (const ulonglong2*)smem_buf;
        unsigned long long acc0[8], acc1[8];
#pragma unroll
        for (int b = 0; b < 8; b++) { acc0[b] = 0ull; acc1[b] = 0ull; }
#pragma unroll
        for (int j = 0; j < 8; j++) {
            const int ko = j * 32 + ks;
#pragma unroll
            for (int b = 0; b < 8; b++) {
                ulonglong2 hv = hp2[b * 256 + ko];   // 4 floats = 2 k-pairs
                FMA2(acc0[b], hv.x, w0p[2 * j + 0]);
                FMA2(acc0[b], hv.y, w0p[2 * j + 1]);
                FMA2(acc1[b], hv.x, w1p[2 * j + 0]);
                FMA2(acc1[b], hv.y, w1p[2 * j + 1]);
            }
        }
        __syncthreads();   // all LDS reads done before scratch overwrite (aliased)
#pragma unroll
        for (int q = 0; q < 8; q++) {
            float2 p0 = upk2(acc0[q]);
            float2 p1 = upk2(acc1[q]);
            scratch[tid * 17 + q]     = p0.x + p0.y;
            scratch[tid * 17 + 8 + q] = p1.x + p1.y;
        }
        __syncthreads();
        if (is_col) {
            float v[32];
#pragma unroll
            for (int q = 0; q < 32; q++) v[q] = scratch[(q * 8 + col_dp) * 17 + col_r];
#pragma unroll
            for (int o = 16; o > 0; o >>= 1)
#pragma unroll
                for (int q = 0; q < 16; q++) if (q < o) v[q] = v[q] + v[q + o];
            const float pre  = v[0] + xp;
            const float hnew = tanhf(pre);
            g_h[(t + 1) & 1][col_off] = hnew;
            out[OFF_H + (size_t)(t + 1) * SLAB + col_off] = hnew;
            const float sg = 1.f / (1.f + expf(-zv));
            out[(size_t)t * SLAB + col_off] = hnew * zv * sg;
        }
        groupbar(gseq, bg);
    }
}

// ---------------- launcher ----------------
extern "C" void kernel_launch(void* const* d_in, const int* in_sizes, int n_in,
                              void* d_out, int out_size) {
    const float* x  = (const float*)d_in[0];
    const float* z  = (const float*)d_in[1];
    const float* h0 = (const float*)d_in[2];
    const float* Wx = (const float*)d_in[3];
    const float* Wh = (const float*)d_in[4];
    const float* lr = (const float*)d_in[5];
    const float* bb = (const float*)d_in[6];
    const float* u0 = (const float*)d_in[7];
    float* out = (float*)d_out;
    (void)in_sizes; (void)n_in; (void)out_size;

    init_kernel<<<1, 256>>>(u0);
    xp_gemm<<<dim3(8, 128), 256>>>(x, Wx, bb);
    scan_kernel<<<NBLK, 256>>>(z, h0, Wh, lr, out);
}

// round 5
// speedup vs baseline: 2.0354x; 1.1147x over previous
#include <cuda_runtime.h>
#include <math.h>

#define T_LEN 1024
#define BATCH 16
#define DIM   1024
#define NBLK  128
#define GRPB  32
#define NGRP  4
#define EPSF  1e-8f
#define MAXRAD 0.999f
#define SLAB  (BATCH * DIM)              // 16384
#define OFF_H ((size_t)T_LEN * SLAB)     // outs first, then h_all

// ---------------- device scratch (no allocs allowed) ----------------
__device__ float    g_Xp[(size_t)T_LEN * SLAB];  // 64 MB: x @ Wx^T + b
__device__ float    g_h[2][SLAB];                // double-buffered hidden state
__device__ float    g_u[DIM];
__device__ float    g_v[DIM];
__device__ float    g_part[NBLK];
__device__ unsigned g_bar;
__device__ unsigned g_barg[NGRP * 32];           // 128B-padded per-group flags

// ---------------- f32x2 helpers (sm_103a packed FFMA2) ----------------
#define FMA2(d, a, b) asm("fma.rn.f32x2 %0, %1, %2, %0;" : "+l"(d) : "l"(a), "l"(b))

__device__ __forceinline__ unsigned long long pk2(float lo, float hi) {
    unsigned long long r;
    asm("mov.b64 %0, {%1, %2};" : "=l"(r) : "f"(lo), "f"(hi));
    return r;
}
__device__ __forceinline__ float2 upk2(unsigned long long v) {
    float lo, hi;
    asm("mov.b64 {%0, %1}, %2;" : "=f"(lo), "=f"(hi) : "l"(v));
    return make_float2(lo, hi);
}

// ---------------- init: reset barriers, seed u0 ----------------
__global__ void init_kernel(const float* __restrict__ u0) {
    if (threadIdx.x == 0) g_bar = 0u;
    if (threadIdx.x < NGRP * 32) g_barg[threadIdx.x] = 0u;
    for (int i = threadIdx.x; i < DIM; i += blockDim.x) g_u[i] = u0[i];
}

// ---------------- Xp = x @ Wx^T + b  (fp32 SGEMM w/ FFMA2, NT) ----------------
__global__ __launch_bounds__(256) void xp_gemm(const float* __restrict__ A,
                                               const float* __restrict__ Wn,
                                               const float* __restrict__ bias) {
    __shared__ float As[8][132];
    __shared__ float Bs[8][132];
    const int bn = blockIdx.x;   // 0..7
    const int bm = blockIdx.y;   // 0..127
    const int tid = threadIdx.x;
    const int tx = tid & 15, ty = tid >> 4;
    const int m0 = bm * 128, n0 = bn * 128;

    unsigned long long acc2[8][4];
#pragma unroll
    for (int i = 0; i < 8; i++)
#pragma unroll
        for (int j = 0; j < 4; j++) acc2[i][j] = 0ull;

    const int lm = tid >> 1;
    const int lk = (tid & 1) * 4;
    const float* ap = A  + (size_t)(m0 + lm) * DIM + lk;
    const float* bp = Wn + (size_t)(n0 + lm) * DIM + lk;

    for (int k0 = 0; k0 < DIM; k0 += 8) {
        float4 av = *(const float4*)(ap + k0);
        float4 bv = *(const float4*)(bp + k0);
        As[lk + 0][lm] = av.x; As[lk + 1][lm] = av.y; As[lk + 2][lm] = av.z; As[lk + 3][lm] = av.w;
        Bs[lk + 0][lm] = bv.x; Bs[lk + 1][lm] = bv.y; Bs[lk + 2][lm] = bv.z; Bs[lk + 3][lm] = bv.w;
        __syncthreads();
#pragma unroll
        for (int k = 0; k < 8; k++) {
            float a[8];
            *(float4*)&a[0] = *(const float4*)&As[k][ty * 8];
            *(float4*)&a[4] = *(const float4*)&As[k][ty * 8 + 4];
            ulonglong2 t0 = *(const ulonglong2*)&Bs[k][tx * 8];
            ulonglong2 t1 = *(const ulonglong2*)&Bs[k][tx * 8 + 4];
#pragma unroll
            for (int i = 0; i < 8; i++) {
                unsigned long long ai = pk2(a[i], a[i]);
                FMA2(acc2[i][0], ai, t0.x);
                FMA2(acc2[i][1], ai, t0.y);
                FMA2(acc2[i][2], ai, t1.x);
                FMA2(acc2[i][3], ai, t1.y);
            }
        }
        __syncthreads();
    }
#pragma unroll
    for (int i = 0; i < 8; i++) {
        const int m = m0 + ty * 8 + i;
        float* cr = g_Xp + (size_t)m * DIM + n0 + tx * 8;
        const float* bs = bias + n0 + tx * 8;
#pragma unroll
        for (int j = 0; j < 4; j++) {
            float2 p = upk2(acc2[i][j]);
            cr[2 * j + 0] = p.x + bs[2 * j + 0];
            cr[2 * j + 1] = p.y + bs[2 * j + 1];
        }
    }
}

// ---------------- barriers ----------------
__device__ __forceinline__ void gridbar(int& seq) {
    seq++;
    __syncthreads();
    if (threadIdx.x == 0) {
        __threadfence();
        atomicAdd(&g_bar, 1u);
        const unsigned tgt = (unsigned)seq * NBLK;
        while (*((volatile unsigned*)&g_bar) < tgt) { }
        __threadfence();
    }
    __syncthreads();
}
__device__ __forceinline__ void groupbar(int& gseq, unsigned* flag) {
    gseq++;
    __syncthreads();
    if (threadIdx.x == 0) {
        asm volatile("red.release.gpu.global.add.u32 [%0], 1;" :: "l"(flag) : "memory");
        const unsigned tgt = (unsigned)gseq * GRPB;
        unsigned v;
        do {
            asm volatile("ld.global.acquire.gpu.u32 %0, [%1];" : "=r"(v) : "l"(flag) : "memory");
        } while (v < tgt);
    }
    __syncthreads();
}

// ---------------- persistent scan kernel ----------------
__global__ __launch_bounds__(256) void scan_kernel(const float* __restrict__ z,
                                                   const float* __restrict__ h0,
                                                   const float* __restrict__ W_h,
                                                   const float* __restrict__ log_radii,
                                                   float* __restrict__ out) {
    __shared__ float hsm[4 * DIM];       // 16 KB: staged h for this group's 4 batches
    __shared__ float scratch[8 * 128];   // 4 KB: cross-warp reduction
    __shared__ float sred[64];

    const int tid  = threadIdx.x;
    const int bid  = blockIdx.x;
    const int lane = tid & 31;
    const int warp = tid >> 5;
    int seq = 0;

    // ======== phase 0: power iteration (3 iters, all 128 blocks) ========
    float sigma = 0.f;
    for (int it = 0; it < 3; it++) {
        {   // v_raw = W^T u ; block owns columns [bid*8, bid*8+8)
            const int j0 = bid * 8;
            float sj[8];
#pragma unroll
            for (int q = 0; q < 8; q++) sj[q] = 0.f;
            for (int i = warp * 32 + lane; i < DIM; i += 256) {
                const float ui = __ldcg(&g_u[i]);
                const float* wr = W_h + (size_t)i * DIM + j0;
                float4 w0 = *(const float4*)wr;
                float4 w1 = *(const float4*)(wr + 4);
                sj[0] = fmaf(w0.x, ui, sj[0]); sj[1] = fmaf(w0.y, ui, sj[1]);
                sj[2] = fmaf(w0.z, ui, sj[2]); sj[3] = fmaf(w0.w, ui, sj[3]);
                sj[4] = fmaf(w1.x, ui, sj[4]); sj[5] = fmaf(w1.y, ui, sj[5]);
                sj[6] = fmaf(w1.z, ui, sj[6]); sj[7] = fmaf(w1.w, ui, sj[7]);
            }
#pragma unroll
            for (int q = 0; q < 8; q++)
#pragma unroll
                for (int o = 16; o > 0; o >>= 1) sj[q] += __shfl_xor_sync(0xffffffffu, sj[q], o);
            if (lane == 0) {
#pragma unroll
                for (int q = 0; q < 8; q++) sred[warp * 8 + q] = sj[q];
            }
            __syncthreads();
            if (tid < 8) {
                float s = 0.f;
#pragma unroll
                for (int w = 0; w < 8; w++) s += sred[w * 8 + tid];
                g_v[j0 + tid] = s;
                scratch[tid] = s * s;
            }
            __syncthreads();
            if (tid == 0) {
                float s = 0.f;
#pragma unroll
                for (int q = 0; q < 8; q++) s += scratch[q];
                g_part[bid] = s;
            }
        }
        gridbar(seq);
        {   // norm(v), normalize own segment
            if (tid == 0) {
                float s = 0.f;
                for (int q = 0; q < NBLK; q++) s += __ldcg(&g_part[q]);
                sred[0] = sqrtf(s);
            }
            __syncthreads();
            const float nrm = sred[0];
            if (tid < 8) g_v[bid * 8 + tid] = __ldcg(&g_v[bid * 8 + tid]) / (nrm + EPSF);
        }
        gridbar(seq);
        {   // u_raw = W v ; one warp per row
            const int i = bid * 8 + warp;
            float s = 0.f;
            const float* wr = W_h + (size_t)i * DIM;
            for (int j = lane * 4; j < DIM; j += 128) {
                float4 wv = *(const float4*)(wr + j);
                float4 vv = __ldcg((const float4*)(g_v + j));
                s = fmaf(wv.x, vv.x, s); s = fmaf(wv.y, vv.y, s);
                s = fmaf(wv.z, vv.z, s); s = fmaf(wv.w, vv.w, s);
            }
#pragma unroll
            for (int o = 16; o > 0; o >>= 1) s += __shfl_xor_sync(0xffffffffu, s, o);
            if (lane == 0) { g_u[i] = s; sred[warp] = s * s; }
            __syncthreads();
            if (tid == 0) {
                float ss = 0.f;
#pragma unroll
                for (int w = 0; w < 8; w++) ss += sred[w];
                g_part[bid] = ss;
            }
        }
        gridbar(seq);
        {   // norm(u); sigma = ||Wv||^2/(||Wv||+eps) == |u·W·v| on last iter
            if (tid == 0) {
                float s = 0.f;
                for (int q = 0; q < NBLK; q++) s += __ldcg(&g_part[q]);
                sred[0] = s;
            }
            __syncthreads();
            const float sumsq = sred[0];
            const float nrm = sqrtf(sumsq);
            if (tid < 8) g_u[bid * 8 + tid] = __ldcg(&g_u[bid * 8 + tid]) / (nrm + EPSF);
            if (it == 2) sigma = sumsq / (nrm + EPSF);
        }
        gridbar(seq);
    }

    // ======== phase 1: group mapping + W_h_eff rows into registers ========
    // 4 independent groups of 32 blocks; group g owns batches [4g,4g+4),
    // block ib within group owns dims [32*ib, 32*ib+32).
    const int g  = bid & 3;
    const int ib = bid >> 2;
    const int dbase = ib * 32;
    const int gbase = g * 4;          // first batch of this group

    const int dp = tid & 15;          // 2 dims per thread
    const int ks = tid >> 4;          // 0..15: k = c*64 + ks*4 + {0..3}
    const int d0 = dbase + dp * 2;
    const int d1 = d0 + 1;

    float sc0, sc1;
    {
        const float r0 = MAXRAD / (1.f + expf(-log_radii[d0]));
        const float r1 = MAXRAD / (1.f + expf(-log_radii[d1]));
        sc0 = r0 / (sigma + EPSF);
        sc1 = r1 / (sigma + EPSF);
    }
    unsigned long long w0p[32], w1p[32];
#pragma unroll
    for (int c = 0; c < 16; c++) {
        const int k = c * 64 + ks * 4;
        float4 a = *(const float4*)(W_h + (size_t)d0 * DIM + k);
        float4 cc = *(const float4*)(W_h + (size_t)d1 * DIM + k);
        w0p[2 * c + 0] = pk2(a.x * sc0, a.y * sc0);
        w0p[2 * c + 1] = pk2(a.z * sc0, a.w * sc0);
        w1p[2 * c + 0] = pk2(cc.x * sc1, cc.y * sc1);
        w1p[2 * c + 1] = pk2(cc.z * sc1, cc.w * sc1);
    }

    // h0 -> g_h[0] and h_all[0] (all 128 blocks cover the slab)
    if (tid < 128) {
        const int idx = bid * 128 + tid;
        const float hv = h0[idx];
        g_h[0][idx] = hv;
        out[OFF_H + idx] = hv;
    }
    gridbar(seq);   // full barrier: h0 writes cross groups

    // collector mapping (tid < 128): b = tid>>5, d = tid&31 (coalesced over d)
    const bool is_col = tid < 128;
    const int col_b = tid >> 5;
    const int col_d = tid & 31;
    const int col_off = (gbase + col_b) * DIM + dbase + col_d;

    unsigned* flag = &g_barg[g * 32];
    int gseq = 0;

    // prefetch t=0 operands
    float xp_cur = 0.f, zv_cur = 0.f;
    if (is_col) { xp_cur = g_Xp[col_off]; zv_cur = z[col_off]; }

    // ======== phase 2: the scan ========
    for (int t = 0; t < T_LEN; t++) {
        // stage h[t] for this group's 4 batches (16 KB, coalesced, L1-bypassing)
        {
            const float4* src = (const float4*)(g_h[t & 1] + gbase * DIM);
            float4* dst = (float4*)hsm;
#pragma unroll
            for (int q = 0; q < 4; q++) dst[tid + q * 256] = __ldcg(src + tid + q * 256);
        }
        __syncthreads();

        const ulonglong2* hp2 = (const ulonglong2*)hsm;
        unsigned long long acc0[4], acc1[4];
#pragma unroll
        for (int b = 0; b < 4; b++) { acc0[b] = 0ull; acc1[b] = 0ull; }
#pragma unroll
        for (int c = 0; c < 16; c++) {
            const int ko = c * 16 + ks;
#pragma unroll
            for (int b = 0; b < 4; b++) {
                ulonglong2 hv = hp2[b * 256 + ko];   // 4 floats = 2 k-pairs
                FMA2(acc0[b], hv.x, w0p[2 * c + 0]);
                FMA2(acc0[b], hv.y, w0p[2 * c + 1]);
                FMA2(acc1[b], hv.x, w1p[2 * c + 0]);
                FMA2(acc1[b], hv.y, w1p[2 * c + 1]);
            }
        }
        // fold k-pair, then fold ks-parity partner (lane ^ 16), then STS
        float f0[4], f1[4];
#pragma unroll
        for (int b = 0; b < 4; b++) {
            float2 p0 = upk2(acc0[b]);
            float2 p1 = upk2(acc1[b]);
            f0[b] = p0.x + p0.y;
            f1[b] = p1.x + p1.y;
            f0[b] += __shfl_xor_sync(0xffffffffu, f0[b], 16);
            f1[b] += __shfl_xor_sync(0xffffffffu, f1[b], 16);
        }
        {
            // lane<16 writes d'=0, lane>=16 writes d'=1: 32 distinct banks
            const int dpr = (lane & 16) ? 1 : 0;
            float* row = &scratch[warp * 128 + dp * 2 + dpr];
            const float* fv = dpr ? f1 : f0;
#pragma unroll
            for (int b = 0; b < 4; b++) row[b * 32] = fv[b];
        }
        __syncthreads();
        if (is_col) {
            float s = scratch[tid];
#pragma unroll
            for (int w = 1; w < 8; w++) s += scratch[w * 128 + tid];
            const float hnew = tanhf(s + xp_cur);
            g_h[(t + 1) & 1][col_off] = hnew;
            out[OFF_H + (size_t)(t + 1) * SLAB + col_off] = hnew;
            const float sg = 1.f / (1.f + expf(-zv_cur));
            out[(size_t)t * SLAB + col_off] = hnew * zv_cur * sg;
            // prefetch t+1 operands; latency hides in the barrier spin
            if (t + 1 < T_LEN) {
                const size_t gi = (size_t)(t + 1) * SLAB + col_off;
                xp_cur = g_Xp[gi];
                zv_cur = z[gi];
            }
        }
        groupbar(gseq, flag);
    }
}

// ---------------- launcher ----------------
extern "C" void kernel_launch(void* const* d_in, const int* in_sizes, int n_in,
                              void* d_out, int out_size) {
    const float* x  = (const float*)d_in[0];
    const float* z  = (const float*)d_in[1];
    const float* h0 = (const float*)d_in[2];
    const float* Wx = (const float*)d_in[3];
    const float* Wh = (const float*)d_in[4];
    const float* lr = (const float*)d_in[5];
    const float* bb = (const float*)d_in[6];
    const float* u0 = (const float*)d_in[7];
    float* out = (float*)d_out;
    (void)in_sizes; (void)n_in; (void)out_size;

    init_kernel<<<1, 256>>>(u0);
    xp_gemm<<<dim3(8, 128), 256>>>(x, Wx, bb);
    scan_kernel<<<NBLK, 256>>>(z, h0, Wh, lr, out);
}